// round 6
// baseline (speedup 1.0000x reference)
#include <cuda_runtime.h>

// Problem constants
#define B_TOTAL  2
#define C_IN     32
#define HDIM     64
#define WDIM     64
#define J_TOTAL  4096
#define S_TOTAL  256
#define HID      64
#define C_OUT    32
#define JPB      8       // 1024 blocks -> ~7/SM, single balanced wave
#define SCHUNK   64      // s-chunk staged in smem (16KB)

// Scratch: Q[b,s,h] = b1[h] - sx*W1[0,h] - sy*W1[1,h] + sum_c v[b,c,idx_s]*W1[2+c,h]
__device__ float g_Q[B_TOTAL * S_TOTAL * HID];

__device__ __forceinline__ float tanhf_hw(float x) {
    float r; asm("tanh.approx.f32 %0, %1;" : "=f"(r) : "f"(x)); return r;
}

// ---------- kernel 1: Q[b,s,h] ----------
__global__ void precompute_q(const float* __restrict__ v,
                             const int* __restrict__ indices,
                             const float* __restrict__ W1,
                             const float* __restrict__ b1) {
    int s = blockIdx.x;
    int b = blockIdx.y;
    int h = threadIdx.x;
    int idx = indices[s] & (J_TOTAL - 1);
    int ix = idx & (WDIM - 1);
    int iy = idx >> 6;
    float sx = ix * (1.0f / 63.0f);
    float sy = iy * (1.0f / 63.0f);
    float acc = b1[h] - sx * W1[h] - sy * W1[HID + h];
    const float* vb = v + (size_t)b * C_IN * J_TOTAL + idx;
#pragma unroll
    for (int c = 0; c < C_IN; c++)
        acc = fmaf(vb[(size_t)c * J_TOTAL], W1[(2 + c) * HID + h], acc);
    g_Q[(b * S_TOTAL + s) * HID + h] = acc;
}

// ---------- kernel 2: main ----------
// gelu_tanh(t) = 0.5*t*(1+tanh(v)), v = sqrt(2/pi)*(t + 0.044715 t^3)
// Loop accumulates acc = sum t*tanh(v) and sq = sum q;
// sum_s gelu = 0.5*(acc + S*a + sq).
__global__ __launch_bounds__(256)
void nystrom_main(const float* __restrict__ W1,
                  const float* __restrict__ W2,
                  const float* __restrict__ b2,
                  float* __restrict__ out) {
    __shared__ float Qs[SCHUNK * HID];     // 16 KB; reused as Gs in epilogue
    __shared__ float W2s[HID * C_OUT];     // 8 KB
    __shared__ float w1x[HID];
    __shared__ float w1y[HID];
    __shared__ float b2s[C_OUT];

    const float C1 = 0.7978845608028654f;  // sqrt(2/pi)
    const float C2 = 0.0356774081f;        // C1*0.044715

    int tid   = threadIdx.x;
    int b     = blockIdx.y;
    int j0    = blockIdx.x * JPB;
    int group = tid >> 6;                  // 0..3
    int h     = tid & 63;

    if (tid < HID) { w1x[tid] = W1[tid]; w1y[tid] = W1[HID + tid]; }
    if (tid >= 64 && tid < 64 + C_OUT) b2s[tid - 64] = b2[tid - 64];
    for (int i = tid; i < HID * C_OUT; i += 256) W2s[i] = W2[i];
    __syncthreads();

    // Each thread owns 2 j's (same h)
    float a[2], acc[2];
#pragma unroll
    for (int i = 0; i < 2; i++) {
        int j = j0 + group * 2 + i;
        float x = (j & (WDIM - 1)) * (1.0f / 63.0f);
        float y = (j >> 6)         * (1.0f / 63.0f);
        a[i] = fmaf(x, w1x[h], y * w1y[h]);
        acc[i] = 0.0f;
    }
    float sq = 0.0f;

    const float* Qg = g_Q + (size_t)b * S_TOTAL * HID;
#pragma unroll
    for (int chunk = 0; chunk < S_TOTAL / SCHUNK; chunk++) {
        __syncthreads();  // protect Qs overwrite
        for (int i = tid; i < SCHUNK * HID; i += 256)
            Qs[i] = Qg[chunk * SCHUNK * HID + i];
        __syncthreads();
#pragma unroll 4
        for (int s = 0; s < SCHUNK; s++) {
            float q = Qs[s * HID + h];
            sq += q;
#pragma unroll
            for (int i = 0; i < 2; i++) {
                float t  = a[i] + q;
                float t2 = t * t;
                float p  = fmaf(C2, t2, C1);
                float v  = t * p;
                float th = tanhf_hw(v);             // MUFU.TANH
                acc[i]   = fmaf(t, th, acc[i]);
            }
        }
    }

    // sum_s gelu = 0.5*(acc + S*a + sq)
    float sums[2];
#pragma unroll
    for (int i = 0; i < 2; i++)
        sums[i] = 0.5f * (acc[i] + fmaf((float)S_TOTAL, a[i], sq));

    // Epilogue
    __syncthreads();
    float* Gs = Qs;                        // overlay (8*64 floats)
#pragma unroll
    for (int i = 0; i < 2; i++)
        Gs[(group * 2 + i) * HID + h] = sums[i];
    __syncthreads();

    // 256 outputs = 8 j * 32 c, one per thread
    {
        int jj = tid >> 5;
        int c  = tid & 31;
        float sum = 0.0f;
#pragma unroll
        for (int hh = 0; hh < HID; hh++)
            sum = fmaf(Gs[jj * HID + hh], W2s[hh * C_OUT + c], sum);
        out[((size_t)b * C_OUT + c) * J_TOTAL + (j0 + jj)] =
            fmaf(sum, 1.0f / (float)S_TOTAL, b2s[c]);
    }
}

extern "C" void kernel_launch(void* const* d_in, const int* in_sizes, int n_in,
                              void* d_out, int out_size) {
    const float* v       = (const float*)d_in[0];
    const int*   indices = (const int*)d_in[1];
    const float* W1      = (const float*)d_in[2];
    const float* b1      = (const float*)d_in[3];
    const float* W2      = (const float*)d_in[4];
    const float* b2      = (const float*)d_in[5];
    float*       out     = (float*)d_out;

    precompute_q<<<dim3(S_TOTAL, B_TOTAL), HID>>>(v, indices, W1, b1);
    nystrom_main<<<dim3(J_TOTAL / JPB, B_TOTAL), 256>>>(W1, W2, b2, out);
}